// round 14
// baseline (speedup 1.0000x reference)
#include <cuda_runtime.h>
#include <cuda_bf16.h>
#include <cstdint>

// Problem shapes (fixed by the dataset)
#define BB   8
#define TT   2048
#define DD   1024
#define HH   8
#define SS   128
#define DH   128      // D / H
#define MAXW 32       // max span width
#define NK   (DD/4)   // 256 16-byte chunks per row
#define RPB  32       // rows per logits block
#define RG   4        // rows per group
#define NGRP (RPB/RG) // 8
#define RING 2        // cp.async ring depth (groups) -- RING=3 regressed, reverted

#define NCHUNK 4
#define ROWS_PER_CHUNK  (BB * TT / NCHUNK)   // 4096
#define LBLK            (ROWS_PER_CHUNK / RPB) // 128 logits blocks per chunk
#define SPANS_PER_CHUNK (BB * SS / NCHUNK)   // 256

// Scratch: logits for every token, [B*T, H] = 512 KB; decoded spans 8 KB
__device__ float g_logits[BB * TT * HH];
__device__ int2  g_span[BB * SS];

// packed fp32x2 FMA (Blackwell; ptxas never emits it from C++)
#define FMA2(d, a, b, c) \
    asm("fma.rn.f32x2 %0, %1, %2, %3;" : "=l"(d) : "l"(a), "l"(b), "l"(c))

static __device__ __forceinline__ float pairsum(unsigned long long x) {
    float lo, hi;
    asm("mov.b64 {%0, %1}, %2;" : "=f"(lo), "=f"(hi) : "l"(x));
    return lo + hi;
}

// ---------------------------------------------------------------------------
// Kernel 1 (per chunk): logits[row, h] = features[row,:] . key_w[h,:] + b[h]
// Proven R12 configuration: RING=2 cp.async ring, 4 rows/group, keys in
// registers, one 31-shfl value-halving butterfly per 4 rows.
// Chunk 0's blocks 0..3 also decode all span bounds into g_span.
// wait_group: pending at iter g = {g, g+1} -> immediate 1, except the last
// iter (single pending group) which must use 0.
// ---------------------------------------------------------------------------
__global__ __launch_bounds__(256, 2)
void logits_kernel(const float* __restrict__ features,
                   const float* __restrict__ key_w,
                   const float* __restrict__ key_b,
                   const int*   __restrict__ begins32,
                   const int*   __restrict__ ends32,
                   int chunk)
{
    __shared__ ulonglong2 ring[RING][RG][256];   // 32 KB
    __shared__ float partial[NGRP][8][32];       // 8 KB

    const int tid     = threadIdx.x;
    const int lane    = tid & 31;
    const int wid     = tid >> 5;
    const int rowbase = chunk * ROWS_PER_CHUNK + blockIdx.x * RPB;

    // ---- side task (chunk 0 only): decode all span bounds.
    // int64-vs-int32 self-detection: genuine int32 ends are >=1 everywhere;
    // int64 high words are zero.
    if (chunk == 0 && blockIdx.x < 4) {
        const int sp = blockIdx.x * 256 + tid;   // 4*256 = 1024 spans
        bool is64 = (ends32[1] == 0) && (ends32[3] == 0) &&
                    (ends32[5] == 0) && (ends32[7] == 0);
        int begin, end;
        if (is64) { begin = begins32[2 * sp]; end = ends32[2 * sp]; }
        else      { begin = begins32[sp];     end = ends32[sp];     }
        g_span[sp] = make_int2(begin, end - begin);
    }

    // ---- keys for this chunk of D, all heads, in registers (32 regs)
    const ulonglong2* kw = reinterpret_cast<const ulonglong2*>(key_w);
    ulonglong2 kk[HH];
    #pragma unroll
    for (int h = 0; h < HH; h++) kk[h] = kw[h * NK + tid];

    const char* fbase = reinterpret_cast<const char*>(features)
                        + (size_t)rowbase * (DD * 4) + (size_t)tid * 16;

    // ---- cp.async pipeline
    #define ISSUE_GROUP(g)                                                      \
    do {                                                                        \
        unsigned int _dst = (unsigned int)__cvta_generic_to_shared(             \
                            &ring[(g) % RING][0][tid]);                         \
        _Pragma("unroll")                                                       \
        for (int _r = 0; _r < RG; _r++) {                                       \
            const char* _src = fbase + (size_t)((g) * RG + _r) * (DD * 4);      \
            asm volatile("cp.async.cg.shared.global [%0], [%1], 16;"            \
                         :: "r"(_dst + _r * (256 * 16)), "l"(_src) : "memory"); \
        }                                                                       \
        asm volatile("cp.async.commit_group;" ::: "memory");                    \
    } while (0)

    ISSUE_GROUP(0);
    ISSUE_GROUP(1);

    #pragma unroll
    for (int g = 0; g < NGRP; g++) {
        // drain group g; last iter has only one pending group -> immediate 0
        if (g == NGRP - 1)
            asm volatile("cp.async.wait_group 0;" ::: "memory");
        else
            asm volatile("cp.async.wait_group 1;" ::: "memory");
        const int buf = g % RING;

        ulonglong2 a[RG];
        #pragma unroll
        for (int r = 0; r < RG; r++) a[r] = ring[buf][r][tid];

        // refill this slot (LDS above already issued)
        if (g + RING < NGRP) ISSUE_GROUP(g + RING);

        unsigned long long acc[HH][RG];
        #pragma unroll
        for (int h = 0; h < HH; h++)
            #pragma unroll
            for (int r = 0; r < RG; r++) acc[h][r] = 0ull;

        #pragma unroll
        for (int h = 0; h < HH; h++) {
            #pragma unroll
            for (int r = 0; r < RG; r++) {
                FMA2(acc[h][r], a[r].x, kk[h].x, acc[h][r]);
                FMA2(acc[h][r], a[r].y, kk[h].y, acc[h][r]);
            }
        }

        // v[idx], idx = h*4 + r  (32 values across 32 lanes)
        float v[32];
        #pragma unroll
        for (int h = 0; h < HH; h++)
            #pragma unroll
            for (int r = 0; r < RG; r++)
                v[h * 4 + r] = pairsum(acc[h][r]);

        // value-halving butterfly: lane l ends holding warp-total of v[l]
        #pragma unroll
        for (int m = 16; m >= 1; m >>= 1) {
            const bool up = (lane & m) != 0;
            #pragma unroll
            for (int i = 0; i < 16; i++) {
                if (i < m) {
                    float send = up ? v[i] : v[i + m];
                    float recv = __shfl_xor_sync(0xffffffffu, send, m);
                    v[i] = (up ? v[i + m] : v[i]) + recv;
                }
            }
        }
        partial[g][wid][lane] = v[0];
    }
    __syncthreads();

    // final combine: 256 threads, one (group, idx) each; sum the 8 warps
    {
        const int g   = tid >> 5;
        const int idx = tid & 31;
        const int h   = idx >> 2;
        const int r   = idx & 3;
        float s = 0.f;
        #pragma unroll
        for (int wq = 0; wq < 8; wq++) s += partial[g][wq][idx];
        g_logits[(size_t)(rowbase + g * RG + r) * HH + h] = s + key_b[h];
    }
    #undef ISSUE_GROUP
}

// ---------------------------------------------------------------------------
// Kernel 2 (per chunk): R9's simple pool -- measured best of three designs.
// Barrier-free: span from g_span (one load), warp h computes head-h softmax
// (lane = t), then batched-8 weighted sum with shfl-broadcast weights.
// ---------------------------------------------------------------------------
__global__ __launch_bounds__(256)
void pool_kernel(const float* __restrict__ features,
                 float*       __restrict__ out,
                 int chunk)
{
    const int tid  = threadIdx.x;
    const int lane = tid & 31;
    const int wid  = tid >> 5;
    const int blk  = chunk * SPANS_PER_CHUNK + blockIdx.x;  // b*S + s
    const int b    = blk >> 7;

    const int2 se   = g_span[blk];
    const int begin = se.x;
    const int w     = se.y;                          // 1..32

    // per-warp softmax for head h = wid; lane = t
    const int h = wid;
    float v = (lane < w)
            ? g_logits[((size_t)b * TT + begin + lane) * HH + h]
            : -3.0e38f;
    float m = v;
    m = fmaxf(m, __shfl_xor_sync(0xffffffffu, m, 16));
    m = fmaxf(m, __shfl_xor_sync(0xffffffffu, m, 8));
    m = fmaxf(m, __shfl_xor_sync(0xffffffffu, m, 4));
    m = fmaxf(m, __shfl_xor_sync(0xffffffffu, m, 2));
    m = fmaxf(m, __shfl_xor_sync(0xffffffffu, m, 1));
    float e = (lane < w) ? __expf(v - m) : 0.f;
    float s = e;
    s += __shfl_xor_sync(0xffffffffu, s, 16);
    s += __shfl_xor_sync(0xffffffffu, s, 8);
    s += __shfl_xor_sync(0xffffffffu, s, 4);
    s += __shfl_xor_sync(0xffffffffu, s, 2);
    s += __shfl_xor_sync(0xffffffffu, s, 1);
    const float wval = e * (1.f / s);                // 0 for lanes >= w

    // weighted sum over span rows, batches of 8 for load MLP
    const float4* vb = reinterpret_cast<const float4*>(features)
                       + ((size_t)b * TT + begin) * NK + tid;
    float4 o = make_float4(0.f, 0.f, 0.f, 0.f);
    int t = 0;
    for (; t + 8 <= w; t += 8) {
        float4 f[8];
        #pragma unroll
        for (int j = 0; j < 8; j++) f[j] = vb[(size_t)(t + j) * NK];
        #pragma unroll
        for (int j = 0; j < 8; j++) {
            float wt = __shfl_sync(0xffffffffu, wval, t + j);
            o.x = fmaf(wt, f[j].x, o.x);
            o.y = fmaf(wt, f[j].y, o.y);
            o.z = fmaf(wt, f[j].z, o.z);
            o.w = fmaf(wt, f[j].w, o.w);
        }
    }
    for (; t < w; t++) {
        float4 f = vb[(size_t)t * NK];
        float wt = __shfl_sync(0xffffffffu, wval, t);
        o.x = fmaf(wt, f.x, o.x);
        o.y = fmaf(wt, f.y, o.y);
        o.z = fmaf(wt, f.z, o.z);
        o.w = fmaf(wt, f.w, o.w);
    }
    reinterpret_cast<float4*>(out)[(size_t)blk * NK + tid] = o;
}

// ---------------------------------------------------------------------------
// Host: chunked fork/join pipeline. Logits chunks on the launch stream; pool
// chunks on a forked stream gated per-chunk by events; join at the end.
// Streams/events are created lazily on the FIRST (correctness, non-capture)
// call and reused; during capture they become graph nodes/edges.
// ---------------------------------------------------------------------------
extern "C" void kernel_launch(void* const* d_in, const int* in_sizes, int n_in,
                              void* d_out, int out_size)
{
    const float* features = (const float*)d_in[0];  // [B,T,D] f32
    const int*   begins   = (const int*)  d_in[1];  // [B,S] int32/int64 (self-detected)
    const int*   ends     = (const int*)  d_in[2];
    const float* key_w    = (const float*)d_in[3];  // [H,D] f32
    const float* key_b    = (const float*)d_in[4];  // [H]   f32
    float*       out      = (float*)d_out;          // [B,S,D] f32

    static cudaStream_t s2 = nullptr;
    static cudaEvent_t  evL[NCHUNK];
    static cudaEvent_t  evJoin = nullptr;
    if (s2 == nullptr) {
        cudaStreamCreateWithFlags(&s2, cudaStreamNonBlocking);
        for (int c = 0; c < NCHUNK; c++)
            cudaEventCreateWithFlags(&evL[c], cudaEventDisableTiming);
        cudaEventCreateWithFlags(&evJoin, cudaEventDisableTiming);
    }

    for (int c = 0; c < NCHUNK; c++) {
        logits_kernel<<<LBLK, 256, 0, 0>>>(features, key_w, key_b,
                                           begins, ends, c);
        cudaEventRecord(evL[c], 0);
        cudaStreamWaitEvent(s2, evL[c], 0);
        pool_kernel<<<SPANS_PER_CHUNK, 256, 0, s2>>>(features, out, c);
    }
    cudaEventRecord(evJoin, s2);
    cudaStreamWaitEvent(0, evJoin, 0);
}